// round 4
// baseline (speedup 1.0000x reference)
#include <cuda_runtime.h>
#include <cuda_bf16.h>
#include <math.h>

#define S_    2048
#define DM_   1024
#define DMLP_ 4096
#define V_    50257
#define H_    16
#define DH_   64
#define L_    2

// ---------------- scratch (static device memory; no allocs allowed) --------
__device__ float g_resid[S_ * DM_];
__device__ float g_x[S_ * DM_];
__device__ float g_q[S_ * DM_];
__device__ float g_k[S_ * DM_];
__device__ float g_v[S_ * DM_];
__device__ float g_z[S_ * DM_];
__device__ float g_scores[(size_t)H_ * S_ * S_];   // 268 MB
__device__ float g_pre[S_ * DMLP_];
__device__ float g_post[S_ * DMLP_];
__device__ float g_wq[DM_ * DM_];
__device__ float g_wk[DM_ * DM_];
__device__ float g_wv[DM_ * DM_];

// ---------------- embed ----------------------------------------------------
__global__ void embed_kernel(const int* __restrict__ tok,
                             const float* __restrict__ WE,
                             const float* __restrict__ Wpos,
                             float* __restrict__ out) {
    int idx = blockIdx.x * 256 + threadIdx.x;          // S_*DM_ total
    int s = idx >> 10;
    int d = idx & 1023;
    out[idx] = WE[(size_t)tok[s] * DM_ + d] + Wpos[idx];
}

// ---------------- repack W_{Q,K,V}[l] : (H,DM,DH) -> row-major [DM, H*DH] --
__global__ void repack_qkv(const float* __restrict__ W, float* __restrict__ o, int l) {
    int idx = blockIdx.x * 256 + threadIdx.x;          // DM_*DM_ total
    int d = idx >> 10;
    int n = idx & 1023;
    int h = n >> 6;
    int e = n & 63;
    o[idx] = W[(size_t)(((l * H_ + h) * DM_) + d) * DH_ + e];
}

// ---------------- layernorm over 1024 cols, one block per row --------------
__global__ void layernorm1024(const float* __restrict__ X,
                              const float* __restrict__ w,
                              const float* __restrict__ b,
                              float* __restrict__ Y) {
    int row = blockIdx.x;
    const float* x = X + (size_t)row * DM_;
    int t = threadIdx.x;                               // 256 threads
    __shared__ float red[8];
    float v[4];
#pragma unroll
    for (int i = 0; i < 4; i++) v[i] = x[t + i * 256];
    float s = v[0] + v[1] + v[2] + v[3];
#pragma unroll
    for (int o = 16; o; o >>= 1) s += __shfl_xor_sync(0xffffffffu, s, o);
    if ((t & 31) == 0) red[t >> 5] = s;
    __syncthreads();
    float mean = 0.f;
#pragma unroll
    for (int j = 0; j < 8; j++) mean += red[j];
    mean *= (1.f / DM_);
    __syncthreads();
    float sq = 0.f;
#pragma unroll
    for (int i = 0; i < 4; i++) { float d = v[i] - mean; sq += d * d; }
#pragma unroll
    for (int o = 16; o; o >>= 1) sq += __shfl_xor_sync(0xffffffffu, sq, o);
    if ((t & 31) == 0) red[t >> 5] = sq;
    __syncthreads();
    float var = 0.f;
#pragma unroll
    for (int j = 0; j < 8; j++) var += red[j];
    var *= (1.f / DM_);
    float inv = rsqrtf(var + 1e-5f);
    float* y = Y + (size_t)row * DM_;
#pragma unroll
    for (int i = 0; i < 4; i++) {
        int c = t + i * 256;
        y[c] = (v[i] - mean) * inv * w[c] + b[c];
    }
}

// ---------------- SGEMM 128x128x8, 8x8 micro, 256 threads, double-buffered --
// C[M,N] = A[M,K] @ B[K,N] (+bias +addv). M % 128 == 0, K % 8 == 0 (true for
// all call sites). N may be ragged (bounds-checked on B loads and stores).
__global__ __launch_bounds__(256, 2)
void sgemm128(const float* __restrict__ A, const float* __restrict__ B,
              const float* __restrict__ bias, const float* __restrict__ addv,
              float* __restrict__ C,
              int M, int N, int K, int lda, int ldb, int ldc) {
    __shared__ float As[2][8][132];
    __shared__ float Bs[2][8][132];
    int tid = threadIdx.x;
    int tx = tid & 15, ty = tid >> 4;
    int bm = blockIdx.y * 128, bn = blockIdx.x * 128;

    int arow = tid >> 1, acol = (tid & 1) * 4;   // A tile: 128 rows x 8 k
    int brow = tid >> 5, bcol = (tid & 31) * 4;  // B tile: 8 k x 128 cols

    const float* Ap = A + (size_t)(bm + arow) * lda + acol;
    // float4 B loads legal when every row pointer is 16B aligned and in range
    bool bvec = ((ldb & 3) == 0) && (bn + bcol + 3 < N);

    float4 ar, br;
    // ---- prefetch tile 0
    ar = *(const float4*)(Ap);
    {
        const float* bp = B + (size_t)brow * ldb + bn + bcol;
        if (bvec) br = *(const float4*)bp;
        else {
            br.x = (bn + bcol + 0 < N) ? bp[0] : 0.f;
            br.y = (bn + bcol + 1 < N) ? bp[1] : 0.f;
            br.z = (bn + bcol + 2 < N) ? bp[2] : 0.f;
            br.w = (bn + bcol + 3 < N) ? bp[3] : 0.f;
        }
    }
    As[0][acol + 0][arow] = ar.x;
    As[0][acol + 1][arow] = ar.y;
    As[0][acol + 2][arow] = ar.z;
    As[0][acol + 3][arow] = ar.w;
    Bs[0][brow][bcol + 0] = br.x;
    Bs[0][brow][bcol + 1] = br.y;
    Bs[0][brow][bcol + 2] = br.z;
    Bs[0][brow][bcol + 3] = br.w;
    __syncthreads();

    float acc[8][8] = {};
    int T = K >> 3;
    int buf = 0;
    for (int t = 0; t < T; t++) {
        // ---- prefetch next tile into registers (overlaps with compute below)
        if (t + 1 < T) {
            int k0n = (t + 1) << 3;
            ar = *(const float4*)(Ap + k0n);
            const float* bp = B + (size_t)(k0n + brow) * ldb + bn + bcol;
            if (bvec) br = *(const float4*)bp;
            else {
                br.x = (bn + bcol + 0 < N) ? bp[0] : 0.f;
                br.y = (bn + bcol + 1 < N) ? bp[1] : 0.f;
                br.z = (bn + bcol + 2 < N) ? bp[2] : 0.f;
                br.w = (bn + bcol + 3 < N) ? bp[3] : 0.f;
            }
        }
        // ---- compute on current buffer
#pragma unroll
        for (int kk = 0; kk < 8; kk++) {
            float a[8], b[8];
            *(float4*)&a[0] = *(const float4*)&As[buf][kk][ty * 4];
            *(float4*)&a[4] = *(const float4*)&As[buf][kk][64 + ty * 4];
            *(float4*)&b[0] = *(const float4*)&Bs[buf][kk][tx * 4];
            *(float4*)&b[4] = *(const float4*)&Bs[buf][kk][64 + tx * 4];
#pragma unroll
            for (int i = 0; i < 8; i++)
#pragma unroll
                for (int j = 0; j < 8; j++) acc[i][j] += a[i] * b[j];
        }
        // ---- publish next tile (disjoint buffer; one barrier per iteration)
        if (t + 1 < T) {
            int nb = buf ^ 1;
            As[nb][acol + 0][arow] = ar.x;
            As[nb][acol + 1][arow] = ar.y;
            As[nb][acol + 2][arow] = ar.z;
            As[nb][acol + 3][arow] = ar.w;
            Bs[nb][brow][bcol + 0] = br.x;
            Bs[nb][brow][bcol + 1] = br.y;
            Bs[nb][brow][bcol + 2] = br.z;
            Bs[nb][brow][bcol + 3] = br.w;
            __syncthreads();
            buf = nb;
        }
    }

#pragma unroll
    for (int i = 0; i < 8; i++) {
        int r = bm + (i < 4 ? ty * 4 + i : 64 + ty * 4 + i - 4);
#pragma unroll
        for (int j = 0; j < 8; j++) {
            int c = bn + (j < 4 ? tx * 4 + j : 64 + tx * 4 + j - 4);
            if (c < N) {
                float v = acc[i][j];
                if (bias) v += bias[c];
                if (addv) v += addv[(size_t)r * ldc + c];
                C[(size_t)r * ldc + c] = v;
            }
        }
    }
}

// ---------------- attention scores: S[h,q,k] = Q·K / 8 (skip masked blocks)-
__global__ void attn_scores(const float* __restrict__ Q, const float* __restrict__ Kmat,
                            float* __restrict__ Sc) {
    int h = blockIdx.z;
    int bm = blockIdx.y * 64, bn = blockIdx.x * 64;
    if (bn > bm + 63) return;               // fully above the diagonal: never read
    __shared__ float Qs[64][68];
    __shared__ float Ks[64][68];
    int tx = threadIdx.x, ty = threadIdx.y;
    int tid = ty * 16 + tx;
#pragma unroll
    for (int i = 0; i < 16; i++) {
        int e = tid + i * 256;              // 0..4095
        int r = e >> 6, c = e & 63;
        Qs[r][c] = Q[(size_t)(bm + r) * DM_ + h * DH_ + c];
        Ks[r][c] = Kmat[(size_t)(bn + r) * DM_ + h * DH_ + c];
    }
    __syncthreads();
    float acc[4][4] = {};
#pragma unroll 8
    for (int kk = 0; kk < 64; kk++) {
        float a[4], b[4];
#pragma unroll
        for (int i = 0; i < 4; i++) a[i] = Qs[ty * 4 + i][kk];
#pragma unroll
        for (int j = 0; j < 4; j++) b[j] = Ks[tx * 4 + j][kk];
#pragma unroll
        for (int i = 0; i < 4; i++)
#pragma unroll
            for (int j = 0; j < 4; j++) acc[i][j] += a[i] * b[j];
    }
    float* Sh = Sc + (size_t)h * S_ * S_;
#pragma unroll
    for (int i = 0; i < 4; i++)
#pragma unroll
        for (int j = 0; j < 4; j++)
            Sh[(size_t)(bm + ty * 4 + i) * S_ + bn + tx * 4 + j] = acc[i][j] * 0.125f;
}

// ---------------- causal softmax over each (h,q) row ------------------------
// Zeros only the masked tail inside this row's diagonal 64-block (attn_z
// never reads beyond it).
__global__ void softmax_causal(float* __restrict__ Sc) {
    int q = blockIdx.x, h = blockIdx.y;
    float* row = Sc + ((size_t)h * S_ + q) * S_;
    int vlen = q + 1;
    int t = threadIdx.x;                    // 256 threads
    __shared__ float red[8];
    float m = -3.4e38f;
    for (int k = t; k < vlen; k += 256) m = fmaxf(m, row[k]);
#pragma unroll
    for (int o = 16; o; o >>= 1) m = fmaxf(m, __shfl_xor_sync(0xffffffffu, m, o));
    if ((t & 31) == 0) red[t >> 5] = m;
    __syncthreads();
    m = red[0];
#pragma unroll
    for (int j = 1; j < 8; j++) m = fmaxf(m, red[j]);
    __syncthreads();
    float s = 0.f;
    for (int k = t; k < vlen; k += 256) {
        float e = expf(row[k] - m);
        row[k] = e;
        s += e;
    }
#pragma unroll
    for (int o = 16; o; o >>= 1) s += __shfl_xor_sync(0xffffffffu, s, o);
    if ((t & 31) == 0) red[t >> 5] = s;
    __syncthreads();
    float tot = 0.f;
#pragma unroll
    for (int j = 0; j < 8; j++) tot += red[j];
    float inv = 1.f / tot;
    for (int k = t; k < vlen; k += 256) row[k] *= inv;
    int blkend = ((q >> 6) + 1) << 6;       // end of this row's diagonal block
    for (int k = vlen + t; k < blkend; k += 256) row[k] = 0.f;
}

// ---------------- Z[q, h*64+e] = sum_k P[h,q,k] * V[k, h*64+e] -------------
__global__ void attn_z(const float* __restrict__ P, const float* __restrict__ Vm,
                       float* __restrict__ Z) {
    int h = blockIdx.z;
    int bm = blockIdx.y * 64;
    const float* Ph = P + (size_t)h * S_ * S_;
    __shared__ float Ps[64][17];    // [row][k]
    __shared__ float Vs[16][68];    // [k][e]
    int tx = threadIdx.x, ty = threadIdx.y;
    int tid = ty * 16 + tx;
    float acc[4][4] = {};
    int kmax = bm + 64;             // causal: keys beyond this block are zero
    for (int k0 = 0; k0 < kmax; k0 += 16) {
#pragma unroll
        for (int i = 0; i < 4; i++) {
            int e = tid + i * 256;
            int r = e >> 4, c = e & 15;
            Ps[r][c] = Ph[(size_t)(bm + r) * S_ + k0 + c];
        }
#pragma unroll
        for (int i = 0; i < 4; i++) {
            int e = tid + i * 256;
            int r = e >> 6, c = e & 63;
            Vs[r][c] = Vm[(size_t)(k0 + r) * DM_ + h * DH_ + c];
        }
        __syncthreads();
#pragma unroll
        for (int kk = 0; kk < 16; kk++) {
            float a[4], b[4];
#pragma unroll
            for (int i = 0; i < 4; i++) a[i] = Ps[ty * 4 + i][kk];
#pragma unroll
            for (int j = 0; j < 4; j++) b[j] = Vs[kk][tx * 4 + j];
#pragma unroll
            for (int i = 0; i < 4; i++)
#pragma unroll
                for (int j = 0; j < 4; j++) acc[i][j] += a[i] * b[j];
        }
        __syncthreads();
    }
#pragma unroll
    for (int i = 0; i < 4; i++)
#pragma unroll
        for (int j = 0; j < 4; j++)
            Z[(size_t)(bm + ty * 4 + i) * DM_ + h * DH_ + tx * 4 + j] = acc[i][j];
}

// ---------------- exact GELU ------------------------------------------------
__global__ void gelu_kernel(const float* __restrict__ X, float* __restrict__ Y, int n) {
    int i = blockIdx.x * 256 + threadIdx.x;
    if (i < n) {
        float x = X[i];
        Y[i] = 0.5f * x * (1.f + erff(x * 0.70710678118654752f));
    }
}

// ---------------- copy ------------------------------------------------------
__global__ void copy_kernel(const float* __restrict__ a, float* __restrict__ b, int n) {
    int i = blockIdx.x * 256 + threadIdx.x;
    if (i < n) b[i] = a[i];
}

// ---------------- host driver ----------------------------------------------
extern "C" void kernel_launch(void* const* d_in, const int* in_sizes, int n_in,
                              void* d_out, int out_size) {
    const int*   tokens = (const int*)  d_in[0];
    const float* W_E    = (const float*)d_in[1];
    const float* W_pos  = (const float*)d_in[2];
    const float* ln1_w  = (const float*)d_in[3];
    const float* ln1_b  = (const float*)d_in[4];
    const float* W_Q    = (const float*)d_in[5];
    const float* b_Q    = (const float*)d_in[6];
    const float* W_K    = (const float*)d_in[7];
    const float* b_K    = (const float*)d_in[8];
    const float* W_V    = (const float*)d_in[9];
    const float* b_V    = (const float*)d_in[10];
    const float* W_O    = (const float*)d_in[11];
    const float* b_O    = (const float*)d_in[12];
    const float* ln2_w  = (const float*)d_in[13];
    const float* ln2_b  = (const float*)d_in[14];
    const float* W_in   = (const float*)d_in[15];
    const float* b_in   = (const float*)d_in[16];
    const float* W_out  = (const float*)d_in[17];
    const float* b_out  = (const float*)d_in[18];
    const float* lnf_w  = (const float*)d_in[19];
    const float* lnf_b  = (const float*)d_in[20];
    const float* W_U    = (const float*)d_in[21];
    const float* b_U    = (const float*)d_in[22];
    float* out = (float*)d_out;

    float *resid, *x, *q, *k, *v, *z, *sc, *pre, *post, *wq, *wk, *wv;
    cudaGetSymbolAddress((void**)&resid, g_resid);
    cudaGetSymbolAddress((void**)&x,     g_x);
    cudaGetSymbolAddress((void**)&q,     g_q);
    cudaGetSymbolAddress((void**)&k,     g_k);
    cudaGetSymbolAddress((void**)&v,     g_v);
    cudaGetSymbolAddress((void**)&z,     g_z);
    cudaGetSymbolAddress((void**)&sc,    g_scores);
    cudaGetSymbolAddress((void**)&pre,   g_pre);
    cudaGetSymbolAddress((void**)&post,  g_post);
    cudaGetSymbolAddress((void**)&wq,    g_wq);
    cudaGetSymbolAddress((void**)&wk,    g_wk);
    cudaGetSymbolAddress((void**)&wv,    g_wv);

    dim3 t2(16, 16);
    dim3 g_dm(DM_ / 128, S_ / 128);               // 2048x1024 GEMMs

    embed_kernel<<<S_ * DM_ / 256, 256>>>(tokens, W_E, W_pos, resid);

    for (int l = 0; l < L_; l++) {
        repack_qkv<<<DM_ * DM_ / 256, 256>>>(W_Q, wq, l);
        repack_qkv<<<DM_ * DM_ / 256, 256>>>(W_K, wk, l);
        repack_qkv<<<DM_ * DM_ / 256, 256>>>(W_V, wv, l);

        layernorm1024<<<S_, 256>>>(resid, ln1_w + l * DM_, ln1_b + l * DM_, x);

        sgemm128<<<g_dm, 256>>>(x, wq, b_Q + l * DM_, nullptr, q, S_, DM_, DM_, DM_, DM_, DM_);
        sgemm128<<<g_dm, 256>>>(x, wk, b_K + l * DM_, nullptr, k, S_, DM_, DM_, DM_, DM_, DM_);
        sgemm128<<<g_dm, 256>>>(x, wv, b_V + l * DM_, nullptr, v, S_, DM_, DM_, DM_, DM_, DM_);

        attn_scores<<<dim3(S_ / 64, S_ / 64, H_), t2>>>(q, k, sc);
        softmax_causal<<<dim3(S_, H_), 256>>>(sc);
        attn_z<<<dim3(1, S_ / 64, H_), t2>>>(sc, v, z);

        sgemm128<<<g_dm, 256>>>(z, W_O + (size_t)l * DM_ * DM_, b_O + l * DM_,
                                resid, resid, S_, DM_, DM_, DM_, DM_, DM_);

        layernorm1024<<<S_, 256>>>(resid, ln2_w + l * DM_, ln2_b + l * DM_, x);

        sgemm128<<<dim3(DMLP_ / 128, S_ / 128), 256>>>(x, W_in + (size_t)l * DM_ * DMLP_,
                                                       b_in + l * DMLP_, nullptr, pre,
                                                       S_, DMLP_, DM_, DM_, DMLP_, DMLP_);
        gelu_kernel<<<S_ * DMLP_ / 256, 256>>>(pre, post, S_ * DMLP_);
        sgemm128<<<g_dm, 256>>>(post, W_out + (size_t)l * DMLP_ * DM_, b_out + l * DM_,
                                resid, resid, S_, DM_, DMLP_, DMLP_, DM_, DM_);
    }

    layernorm1024<<<S_, 256>>>(resid, lnf_w, lnf_b, x);
    sgemm128<<<dim3((V_ + 127) / 128, S_ / 128), 256>>>(x, W_U, b_U, nullptr, out,
                                                        S_, V_, DM_, DM_, V_, V_);

    copy_kernel<<<S_ * DM_ / 256, 256>>>(resid, out + (size_t)S_ * V_, S_ * DM_);
    copy_kernel<<<S_ * DMLP_ / 256, 256>>>(post, out + (size_t)S_ * V_ + S_ * DM_, S_ * DMLP_);
}

// round 7
// speedup vs baseline: 1.2212x; 1.2212x over previous
#include <cuda_runtime.h>
#include <cuda_bf16.h>
#include <math.h>
#include <stdint.h>

#define S_    2048
#define DM_   1024
#define DMLP_ 4096
#define V_    50257
#define H_    16
#define DH_   64
#define L_    2

// ---------------- scratch (static device memory; no allocs allowed) --------
__device__ float g_resid[S_ * DM_];
__device__ float g_x[S_ * DM_];
__device__ float g_q[S_ * DM_];
__device__ float g_k[S_ * DM_];
__device__ float g_v[S_ * DM_];
__device__ float g_z[S_ * DM_];
__device__ float g_scores[(size_t)H_ * S_ * S_];   // 268 MB
__device__ float g_pre[S_ * DMLP_];
__device__ float g_post[S_ * DMLP_];
__device__ float g_wq[DM_ * DM_];
__device__ float g_wk[DM_ * DM_];
__device__ float g_wv[DM_ * DM_];

// ---------------- embed ----------------------------------------------------
__global__ void embed_kernel(const int* __restrict__ tok,
                             const float* __restrict__ WE,
                             const float* __restrict__ Wpos,
                             float* __restrict__ out) {
    int idx = blockIdx.x * 256 + threadIdx.x;
    int s = idx >> 10;
    int d = idx & 1023;
    out[idx] = WE[(size_t)tok[s] * DM_ + d] + Wpos[idx];
}

// ---------------- repack W_{Q,K,V}[l] : (H,DM,DH) -> row-major [DM, H*DH] --
__global__ void repack_qkv(const float* __restrict__ W, float* __restrict__ o, int l) {
    int idx = blockIdx.x * 256 + threadIdx.x;
    int d = idx >> 10;
    int n = idx & 1023;
    int h = n >> 6;
    int e = n & 63;
    o[idx] = W[(size_t)(((l * H_ + h) * DM_) + d) * DH_ + e];
}

// ---------------- layernorm over 1024 cols, one block per row --------------
__global__ void layernorm1024(const float* __restrict__ X,
                              const float* __restrict__ w,
                              const float* __restrict__ b,
                              float* __restrict__ Y) {
    int row = blockIdx.x;
    const float* x = X + (size_t)row * DM_;
    int t = threadIdx.x;
    __shared__ float red[8];
    float v[4];
#pragma unroll
    for (int i = 0; i < 4; i++) v[i] = x[t + i * 256];
    float s = v[0] + v[1] + v[2] + v[3];
#pragma unroll
    for (int o = 16; o; o >>= 1) s += __shfl_xor_sync(0xffffffffu, s, o);
    if ((t & 31) == 0) red[t >> 5] = s;
    __syncthreads();
    float mean = 0.f;
#pragma unroll
    for (int j = 0; j < 8; j++) mean += red[j];
    mean *= (1.f / DM_);
    __syncthreads();
    float sq = 0.f;
#pragma unroll
    for (int i = 0; i < 4; i++) { float d = v[i] - mean; sq += d * d; }
#pragma unroll
    for (int o = 16; o; o >>= 1) sq += __shfl_xor_sync(0xffffffffu, sq, o);
    if ((t & 31) == 0) red[t >> 5] = sq;
    __syncthreads();
    float var = 0.f;
#pragma unroll
    for (int j = 0; j < 8; j++) var += red[j];
    var *= (1.f / DM_);
    float inv = rsqrtf(var + 1e-5f);
    float* y = Y + (size_t)row * DM_;
#pragma unroll
    for (int i = 0; i < 4; i++) {
        int c = t + i * 256;
        y[c] = (v[i] - mean) * inv * w[c] + b[c];
    }
}

// ---------------- tf32 helpers ----------------------------------------------
__device__ __forceinline__ uint32_t f2tf32(float x) {
    uint32_t r;
    asm("cvt.rna.tf32.f32 %0, %1;" : "=r"(r) : "f"(x));
    return r;
}
__device__ __forceinline__ void split_tf32(float x, uint32_t& hi, uint32_t& lo) {
    hi = f2tf32(x);
    lo = f2tf32(x - __uint_as_float(hi));
}
__device__ __forceinline__ void mma_tf32(float4& d, const uint32_t a[4], const uint32_t b[2]) {
    asm volatile(
        "mma.sync.aligned.m16n8k8.row.col.f32.tf32.tf32.f32 "
        "{%0,%1,%2,%3}, {%4,%5,%6,%7}, {%8,%9}, {%0,%1,%2,%3};"
        : "+f"(d.x), "+f"(d.y), "+f"(d.z), "+f"(d.w)
        : "r"(a[0]), "r"(a[1]), "r"(a[2]), "r"(a[3]), "r"(b[0]), "r"(b[1]));
}

// ---------------- tensor-core GEMM 128x128x16, 3xTF32 (fp32 accuracy) -------
// C[M,N] = A[M,K] @ B[K,N] (+bias +addv). M % 128 == 0, K % 16 == 0,
// lda % 4 == 0 (true at all call sites). N ragged OK (bounds-checked).
__global__ __launch_bounds__(256)
void tgemm128(const float* __restrict__ A, const float* __restrict__ B,
              const float* __restrict__ bias, const float* __restrict__ addv,
              float* __restrict__ C,
              int M, int N, int K, int lda, int ldb, int ldc) {
    __shared__ float As[2][128][20];   // [m][k], pad to 20 for bank spread
    __shared__ float Bs[2][16][132];   // [k][n]

    int tid  = threadIdx.x;
    int lane = tid & 31;
    int warp = tid >> 5;
    int g    = lane >> 2;          // group id 0..7
    int tig  = lane & 3;           // thread in group 0..3
    int wm   = warp >> 2;          // 0..1
    int wn   = warp & 3;           // 0..3
    int bm = blockIdx.y * 128, bn = blockIdx.x * 128;

    float4 pa[2], pb[2];

    // ---- global prefetch (tile at k0) into registers
    auto loadG = [&](int k0) {
#pragma unroll
        for (int i = 0; i < 2; i++) {
            int idx = tid * 2 + i;
            int r = idx >> 2, c = (idx & 3) * 4;              // A: 128 x 16
            pa[i] = *(const float4*)(A + (size_t)(bm + r) * lda + k0 + c);
        }
#pragma unroll
        for (int i = 0; i < 2; i++) {
            int idx = tid * 2 + i;
            int r = idx >> 5, c = (idx & 31) * 4;             // B: 16 x 128
            const float* bp = B + (size_t)(k0 + r) * ldb + bn + c;
            if (((ldb & 3) == 0) && (bn + c + 3 < N)) {
                pb[i] = *(const float4*)bp;
            } else {
                pb[i].x = (bn + c + 0 < N) ? bp[0] : 0.f;
                pb[i].y = (bn + c + 1 < N) ? bp[1] : 0.f;
                pb[i].z = (bn + c + 2 < N) ? bp[2] : 0.f;
                pb[i].w = (bn + c + 3 < N) ? bp[3] : 0.f;
            }
        }
    };
    auto storeS = [&](int buf) {
#pragma unroll
        for (int i = 0; i < 2; i++) {
            int idx = tid * 2 + i;
            int r = idx >> 2, c = (idx & 3) * 4;
            *(float4*)&As[buf][r][c] = pa[i];
        }
#pragma unroll
        for (int i = 0; i < 2; i++) {
            int idx = tid * 2 + i;
            int r = idx >> 5, c = (idx & 31) * 4;
            *(float4*)&Bs[buf][r][c] = pb[i];
        }
    };

    loadG(0);
    storeS(0);
    __syncthreads();

    float4 acc[4][4];
#pragma unroll
    for (int mt = 0; mt < 4; mt++)
#pragma unroll
        for (int nt = 0; nt < 4; nt++) acc[mt][nt] = make_float4(0.f, 0.f, 0.f, 0.f);

    int T = K >> 4;
    int buf = 0;
    for (int t = 0; t < T; t++) {
        if (t + 1 < T) loadG((t + 1) << 4);

        // ---- compute on current buffer: two k8 steps
#pragma unroll
        for (int ks = 0; ks < 2; ks++) {
            int kb = ks * 8;
            uint32_t Ah[4][4], Al[4][4], Bh[4][2], Bl[4][2];
#pragma unroll
            for (int mt = 0; mt < 4; mt++)
#pragma unroll
                for (int r = 0; r < 4; r++) {
                    int row = wm * 64 + mt * 16 + g + (r & 1) * 8;
                    int col = kb + tig + (r >> 1) * 4;
                    split_tf32(As[buf][row][col], Ah[mt][r], Al[mt][r]);
                }
#pragma unroll
            for (int nt = 0; nt < 4; nt++)
#pragma unroll
                for (int r = 0; r < 2; r++) {
                    int kr = kb + tig + r * 4;
                    int col = wn * 32 + nt * 8 + g;
                    split_tf32(Bs[buf][kr][col], Bh[nt][r], Bl[nt][r]);
                }
            // 3xTF32: hi*hi + hi*lo + lo*hi
#pragma unroll
            for (int mt = 0; mt < 4; mt++)
#pragma unroll
                for (int nt = 0; nt < 4; nt++) mma_tf32(acc[mt][nt], Ah[mt], Bh[nt]);
#pragma unroll
            for (int mt = 0; mt < 4; mt++)
#pragma unroll
                for (int nt = 0; nt < 4; nt++) mma_tf32(acc[mt][nt], Ah[mt], Bl[nt]);
#pragma unroll
            for (int mt = 0; mt < 4; mt++)
#pragma unroll
                for (int nt = 0; nt < 4; nt++) mma_tf32(acc[mt][nt], Al[mt], Bh[nt]);
        }

        if (t + 1 < T) {
            int nb = buf ^ 1;
            storeS(nb);
            __syncthreads();
            buf = nb;
        }
    }

    // ---- epilogue
#pragma unroll
    for (int mt = 0; mt < 4; mt++) {
        int row0 = bm + wm * 64 + mt * 16 + g;
#pragma unroll
        for (int nt = 0; nt < 4; nt++) {
            int col0 = bn + wn * 32 + nt * 8 + tig * 2;
            float vals[4] = {acc[mt][nt].x, acc[mt][nt].y, acc[mt][nt].z, acc[mt][nt].w};
#pragma unroll
            for (int half = 0; half < 2; half++) {
                int r = row0 + half * 8;
#pragma unroll
                for (int jj = 0; jj < 2; jj++) {
                    int c = col0 + jj;
                    if (c < N) {
                        float v = vals[half * 2 + jj];
                        if (bias) v += bias[c];
                        if (addv) v += addv[(size_t)r * ldc + c];
                        C[(size_t)r * ldc + c] = v;
                    }
                }
            }
        }
    }
}

// ---------------- attention scores: S[h,q,k] = Q·K / 8 (skip masked blocks)-
__global__ void attn_scores(const float* __restrict__ Q, const float* __restrict__ Kmat,
                            float* __restrict__ Sc) {
    int h = blockIdx.z;
    int bm = blockIdx.y * 64, bn = blockIdx.x * 64;
    if (bn > bm + 63) return;               // fully above the diagonal: never read
    __shared__ float Qs[64][68];
    __shared__ float Ks[64][68];
    int tx = threadIdx.x, ty = threadIdx.y;
    int tid = ty * 16 + tx;
#pragma unroll
    for (int i = 0; i < 16; i++) {
        int e = tid + i * 256;
        int r = e >> 6, c = e & 63;
        Qs[r][c] = Q[(size_t)(bm + r) * DM_ + h * DH_ + c];
        Ks[r][c] = Kmat[(size_t)(bn + r) * DM_ + h * DH_ + c];
    }
    __syncthreads();
    float acc[4][4] = {};
#pragma unroll 8
    for (int kk = 0; kk < 64; kk++) {
        float a[4], b[4];
#pragma unroll
        for (int i = 0; i < 4; i++) a[i] = Qs[ty * 4 + i][kk];
#pragma unroll
        for (int j = 0; j < 4; j++) b[j] = Ks[tx * 4 + j][kk];
#pragma unroll
        for (int i = 0; i < 4; i++)
#pragma unroll
            for (int j = 0; j < 4; j++) acc[i][j] += a[i] * b[j];
    }
    float* Sh = Sc + (size_t)h * S_ * S_;
#pragma unroll
    for (int i = 0; i < 4; i++)
#pragma unroll
        for (int j = 0; j < 4; j++)
            Sh[(size_t)(bm + ty * 4 + i) * S_ + bn + tx * 4 + j] = acc[i][j] * 0.125f;
}

// ---------------- causal softmax over each (h,q) row ------------------------
__global__ void softmax_causal(float* __restrict__ Sc) {
    int q = blockIdx.x, h = blockIdx.y;
    float* row = Sc + ((size_t)h * S_ + q) * S_;
    int vlen = q + 1;
    int t = threadIdx.x;
    __shared__ float red[8];
    float m = -3.4e38f;
    for (int k = t; k < vlen; k += 256) m = fmaxf(m, row[k]);
#pragma unroll
    for (int o = 16; o; o >>= 1) m = fmaxf(m, __shfl_xor_sync(0xffffffffu, m, o));
    if ((t & 31) == 0) red[t >> 5] = m;
    __syncthreads();
    m = red[0];
#pragma unroll
    for (int j = 1; j < 8; j++) m = fmaxf(m, red[j]);
    __syncthreads();
    float s = 0.f;
    for (int k = t; k < vlen; k += 256) {
        float e = expf(row[k] - m);
        row[k] = e;
        s += e;
    }
#pragma unroll
    for (int o = 16; o; o >>= 1) s += __shfl_xor_sync(0xffffffffu, s, o);
    if ((t & 31) == 0) red[t >> 5] = s;
    __syncthreads();
    float tot = 0.f;
#pragma unroll
    for (int j = 0; j < 8; j++) tot += red[j];
    float inv = 1.f / tot;
    for (int k = t; k < vlen; k += 256) row[k] *= inv;
    int blkend = ((q >> 6) + 1) << 6;       // end of this row's diagonal block
    for (int k = vlen + t; k < blkend; k += 256) row[k] = 0.f;
}

// ---------------- Z[q, h*64+e] = sum_k P[h,q,k] * V[k, h*64+e] -------------
__global__ void attn_z(const float* __restrict__ P, const float* __restrict__ Vm,
                       float* __restrict__ Z) {
    int h = blockIdx.z;
    int bm = blockIdx.y * 64;
    const float* Ph = P + (size_t)h * S_ * S_;
    __shared__ float Ps[64][17];
    __shared__ float Vs[16][68];
    int tx = threadIdx.x, ty = threadIdx.y;
    int tid = ty * 16 + tx;
    float acc[4][4] = {};
    int kmax = bm + 64;
    for (int k0 = 0; k0 < kmax; k0 += 16) {
#pragma unroll
        for (int i = 0; i < 4; i++) {
            int e = tid + i * 256;
            int r = e >> 4, c = e & 15;
            Ps[r][c] = Ph[(size_t)(bm + r) * S_ + k0 + c];
        }
#pragma unroll
        for (int i = 0; i < 4; i++) {
            int e = tid + i * 256;
            int r = e >> 6, c = e & 63;
            Vs[r][c] = Vm[(size_t)(k0 + r) * DM_ + h * DH_ + c];
        }
        __syncthreads();
#pragma unroll
        for (int kk = 0; kk < 16; kk++) {
            float a[4], b[4];
#pragma unroll
            for (int i = 0; i < 4; i++) a[i] = Ps[ty * 4 + i][kk];
#pragma unroll
            for (int j = 0; j < 4; j++) b[j] = Vs[kk][tx * 4 + j];
#pragma unroll
            for (int i = 0; i < 4; i++)
#pragma unroll
                for (int j = 0; j < 4; j++) acc[i][j] += a[i] * b[j];
        }
        __syncthreads();
    }
#pragma unroll
    for (int i = 0; i < 4; i++)
#pragma unroll
        for (int j = 0; j < 4; j++)
            Z[(size_t)(bm + ty * 4 + i) * DM_ + h * DH_ + tx * 4 + j] = acc[i][j];
}

// ---------------- exact GELU ------------------------------------------------
__global__ void gelu_kernel(const float* __restrict__ X, float* __restrict__ Y, int n) {
    int i = blockIdx.x * 256 + threadIdx.x;
    if (i < n) {
        float x = X[i];
        Y[i] = 0.5f * x * (1.f + erff(x * 0.70710678118654752f));
    }
}

// ---------------- copy ------------------------------------------------------
__global__ void copy_kernel(const float* __restrict__ a, float* __restrict__ b, int n) {
    int i = blockIdx.x * 256 + threadIdx.x;
    if (i < n) b[i] = a[i];
}

// ---------------- host driver ----------------------------------------------
extern "C" void kernel_launch(void* const* d_in, const int* in_sizes, int n_in,
                              void* d_out, int out_size) {
    const int*   tokens = (const int*)  d_in[0];
    const float* W_E    = (const float*)d_in[1];
    const float* W_pos  = (const float*)d_in[2];
    const float* ln1_w  = (const float*)d_in[3];
    const float* ln1_b  = (const float*)d_in[4];
    const float* W_Q    = (const float*)d_in[5];
    const float* b_Q    = (const float*)d_in[6];
    const float* W_K    = (const float*)d_in[7];
    const float* b_K    = (const float*)d_in[8];
    const float* W_V    = (const float*)d_in[9];
    const float* b_V    = (const float*)d_in[10];
    const float* W_O    = (const float*)d_in[11];
    const float* b_O    = (const float*)d_in[12];
    const float* ln2_w  = (const float*)d_in[13];
    const float* ln2_b  = (const float*)d_in[14];
    const float* W_in   = (const float*)d_in[15];
    const float* b_in   = (const float*)d_in[16];
    const float* W_out  = (const float*)d_in[17];
    const float* b_out  = (const float*)d_in[18];
    const float* lnf_w  = (const float*)d_in[19];
    const float* lnf_b  = (const float*)d_in[20];
    const float* W_U    = (const float*)d_in[21];
    const float* b_U    = (const float*)d_in[22];
    float* out = (float*)d_out;

    float *resid, *x, *q, *k, *v, *z, *sc, *pre, *post, *wq, *wk, *wv;
    cudaGetSymbolAddress((void**)&resid, g_resid);
    cudaGetSymbolAddress((void**)&x,     g_x);
    cudaGetSymbolAddress((void**)&q,     g_q);
    cudaGetSymbolAddress((void**)&k,     g_k);
    cudaGetSymbolAddress((void**)&v,     g_v);
    cudaGetSymbolAddress((void**)&z,     g_z);
    cudaGetSymbolAddress((void**)&sc,    g_scores);
    cudaGetSymbolAddress((void**)&pre,   g_pre);
    cudaGetSymbolAddress((void**)&post,  g_post);
    cudaGetSymbolAddress((void**)&wq,    g_wq);
    cudaGetSymbolAddress((void**)&wk,    g_wk);
    cudaGetSymbolAddress((void**)&wv,    g_wv);

    dim3 t2(16, 16);
    dim3 g_dm(DM_ / 128, S_ / 128);

    embed_kernel<<<S_ * DM_ / 256, 256>>>(tokens, W_E, W_pos, resid);

    for (int l = 0; l < L_; l++) {
        repack_qkv<<<DM_ * DM_ / 256, 256>>>(W_Q, wq, l);
        repack_qkv<<<DM_ * DM_ / 256, 256>>>(W_K, wk, l);
        repack_qkv<<<DM_ * DM_ / 256, 256>>>(W_V, wv, l);

        layernorm1024<<<S_, 256>>>(resid, ln1_w + l * DM_, ln1_b + l * DM_, x);

        tgemm128<<<g_dm, 256>>>(x, wq, b_Q + l * DM_, nullptr, q, S_, DM_, DM_, DM_, DM_, DM_);
        tgemm128<<<g_dm, 256>>>(x, wk, b_K + l * DM_, nullptr, k, S_, DM_, DM_, DM_, DM_, DM_);
        tgemm128<<<g_dm, 256>>>(x, wv, b_V + l * DM_, nullptr, v, S_, DM_, DM_, DM_, DM_, DM_);

        attn_scores<<<dim3(S_ / 64, S_ / 64, H_), t2>>>(q, k, sc);
        softmax_causal<<<dim3(S_, H_), 256>>>(sc);
        attn_z<<<dim3(1, S_ / 64, H_), t2>>>(sc, v, z);

        tgemm128<<<g_dm, 256>>>(z, W_O + (size_t)l * DM_ * DM_, b_O + l * DM_,
                                resid, resid, S_, DM_, DM_, DM_, DM_, DM_);

        layernorm1024<<<S_, 256>>>(resid, ln2_w + l * DM_, ln2_b + l * DM_, x);

        tgemm128<<<dim3(DMLP_ / 128, S_ / 128), 256>>>(x, W_in + (size_t)l * DM_ * DMLP_,
                                                       b_in + l * DMLP_, nullptr, pre,
                                                       S_, DMLP_, DM_, DM_, DMLP_, DMLP_);
        gelu_kernel<<<S_ * DMLP_ / 256, 256>>>(pre, post, S_ * DMLP_);
        tgemm128<<<g_dm, 256>>>(post, W_out + (size_t)l * DMLP_ * DM_, b_out + l * DM_,
                                resid, resid, S_, DM_, DMLP_, DMLP_, DM_, DM_);
    }

    layernorm1024<<<S_, 256>>>(resid, lnf_w, lnf_b, x);
    tgemm128<<<dim3((V_ + 127) / 128, S_ / 128), 256>>>(x, W_U, b_U, nullptr, out,
                                                        S_, V_, DM_, DM_, V_, V_);

    copy_kernel<<<S_ * DM_ / 256, 256>>>(resid, out + (size_t)S_ * V_, S_ * DM_);
    copy_kernel<<<S_ * DMLP_ / 256, 256>>>(post, out + (size_t)S_ * V_ + S_ * DM_, S_ * DMLP_);
}

// round 14
// speedup vs baseline: 1.3101x; 1.0728x over previous
#include <cuda_runtime.h>
#include <cuda_bf16.h>
#include <math.h>
#include <stdint.h>

#define S_    2048
#define DM_   1024
#define DMLP_ 4096
#define V_    50257
#define H_    16
#define DH_   64
#define L_    2

// ---------------- scratch (static device memory; no allocs allowed) --------
__device__ float g_resid[S_ * DM_];
__device__ float g_x[S_ * DM_];
__device__ float g_q[S_ * DM_];
__device__ float g_k[S_ * DM_];
__device__ float g_v[S_ * DM_];
__device__ float g_z[S_ * DM_];
__device__ float g_scores[(size_t)H_ * S_ * S_];   // 268 MB
__device__ float g_pre[S_ * DMLP_];
__device__ float g_post[S_ * DMLP_];
// tf32-split staging (hi/lo hold tf32-valued fp32)
__device__ float g_Ah[S_ * DMLP_];                 // max A = post (2048x4096)
__device__ float g_Al[S_ * DMLP_];
__device__ float g_Bh[DM_ * V_];                   // max B = W_U (1024x50257)
__device__ float g_Bl[DM_ * V_];

// ---------------- tf32 helpers ----------------------------------------------
__device__ __forceinline__ uint32_t f2tf32(float x) {
    uint32_t r;
    asm("cvt.rna.tf32.f32 %0, %1;" : "=r"(r) : "f"(x));
    return r;
}
__device__ __forceinline__ void split2(float x, float& h, float& l) {
    h = __uint_as_float(f2tf32(x));
    l = __uint_as_float(f2tf32(x - h));
}

// ---------------- embed ----------------------------------------------------
__global__ void embed_kernel(const int* __restrict__ tok,
                             const float* __restrict__ WE,
                             const float* __restrict__ Wpos,
                             float* __restrict__ out) {
    int idx = blockIdx.x * 256 + threadIdx.x;
    int s = idx >> 10;
    int d = idx & 1023;
    out[idx] = WE[(size_t)tok[s] * DM_ + d] + Wpos[idx];
}

// ---------------- elementwise tf32 split (float4), n % 4 == 0 ---------------
__global__ void split_kernel(const float* __restrict__ X,
                             float* __restrict__ hi, float* __restrict__ lo, int n4) {
    int i = blockIdx.x * 256 + threadIdx.x;
    if (i < n4) {
        float4 x = ((const float4*)X)[i];
        float4 h, l;
        split2(x.x, h.x, l.x);
        split2(x.y, h.y, l.y);
        split2(x.z, h.z, l.z);
        split2(x.w, h.w, l.w);
        ((float4*)hi)[i] = h;
        ((float4*)lo)[i] = l;
    }
}

// ------- repack W_{Q,K,V}[l] (H,DM,DH) -> [DM,H*DH] fused with tf32 split ---
__global__ void repack_split_qkv(const float* __restrict__ W,
                                 float* __restrict__ hi, float* __restrict__ lo, int l) {
    int idx = blockIdx.x * 256 + threadIdx.x;     // DM_*DM_
    int d = idx >> 10;
    int n = idx & 1023;
    int h = n >> 6;
    int e = n & 63;
    float x = W[(size_t)(((l * H_ + h) * DM_) + d) * DH_ + e];
    float xh, xl;
    split2(x, xh, xl);
    hi[idx] = xh;
    lo[idx] = xl;
}

// ---------------- layernorm over 1024 cols, one block per row --------------
__global__ void layernorm1024(const float* __restrict__ X,
                              const float* __restrict__ w,
                              const float* __restrict__ b,
                              float* __restrict__ Y) {
    int row = blockIdx.x;
    const float* x = X + (size_t)row * DM_;
    int t = threadIdx.x;
    __shared__ float red[8];
    float v[4];
#pragma unroll
    for (int i = 0; i < 4; i++) v[i] = x[t + i * 256];
    float s = v[0] + v[1] + v[2] + v[3];
#pragma unroll
    for (int o = 16; o; o >>= 1) s += __shfl_xor_sync(0xffffffffu, s, o);
    if ((t & 31) == 0) red[t >> 5] = s;
    __syncthreads();
    float mean = 0.f;
#pragma unroll
    for (int j = 0; j < 8; j++) mean += red[j];
    mean *= (1.f / DM_);
    __syncthreads();
    float sq = 0.f;
#pragma unroll
    for (int i = 0; i < 4; i++) { float d = v[i] - mean; sq += d * d; }
#pragma unroll
    for (int o = 16; o; o >>= 1) sq += __shfl_xor_sync(0xffffffffu, sq, o);
    if ((t & 31) == 0) red[t >> 5] = sq;
    __syncthreads();
    float var = 0.f;
#pragma unroll
    for (int j = 0; j < 8; j++) var += red[j];
    var *= (1.f / DM_);
    float inv = rsqrtf(var + 1e-5f);
    float* y = Y + (size_t)row * DM_;
#pragma unroll
    for (int i = 0; i < 4; i++) {
        int c = t + i * 256;
        y[c] = (v[i] - mean) * inv * w[c] + b[c];
    }
}

// ---------------- mma + cp.async helpers ------------------------------------
__device__ __forceinline__ void mma_tf32(float4& d, const uint32_t a[4], const uint32_t b[2]) {
    asm volatile(
        "mma.sync.aligned.m16n8k8.row.col.f32.tf32.tf32.f32 "
        "{%0,%1,%2,%3}, {%4,%5,%6,%7}, {%8,%9}, {%0,%1,%2,%3};"
        : "+f"(d.x), "+f"(d.y), "+f"(d.z), "+f"(d.w)
        : "r"(a[0]), "r"(a[1]), "r"(a[2]), "r"(a[3]), "r"(b[0]), "r"(b[1]));
}
__device__ __forceinline__ void cpa16(uint32_t dst, const void* src) {
    asm volatile("cp.async.ca.shared.global [%0], [%1], 16;" :: "r"(dst), "l"(src));
}
__device__ __forceinline__ void cpa4(uint32_t dst, const void* src) {
    asm volatile("cp.async.ca.shared.global [%0], [%1], 4;" :: "r"(dst), "l"(src));
}
__device__ __forceinline__ uint32_t smem_u32(const void* p) {
    uint32_t a;
    asm("{ .reg .u64 t; cvta.to.shared.u64 t, %1; cvt.u32.u64 %0, t; }" : "=r"(a) : "l"(p));
    return a;
}

// -------- tensor-core GEMM, presplit 3xTF32, cp.async double-buffered -------
// C = A @ B (+bias +addv). Operands given as tf32 hi/lo fp32 arrays.
// M%128==0, K%16==0, lda%4==0. N ragged OK.
// smem layout (floats): AH[2][128][20] | AL[2][128][20] | BH[2][16][132] | BL[2][16][132]
#define OFF_AH 0
#define OFF_AL 5120
#define OFF_BH 10240
#define OFF_BL 14464
#define SM_FLOATS 18688
#define SMEM_TG (SM_FLOATS * 4)

__global__ __launch_bounds__(256, 2)
void t32gemm(const float* __restrict__ Ah, const float* __restrict__ Al,
             const float* __restrict__ Bh, const float* __restrict__ Bl,
             const float* __restrict__ bias, const float* __restrict__ addv,
             float* __restrict__ C, int M, int N, int K, int lda, int ldb, int ldc) {
    extern __shared__ float sm[];
    uint32_t sbase = smem_u32(sm);

    int tid  = threadIdx.x;
    int lane = tid & 31;
    int warp = tid >> 5;
    int g    = lane >> 2;
    int tig  = lane & 3;
    int wm   = warp >> 2;
    int wn   = warp & 3;
    int bm = blockIdx.x * 128, bn = blockIdx.y * 128;

    // ---- async tile load: A (16B) + B (4B, guarded)
    auto load_tiles = [&](int k0, int buf) {
        int bufA = buf * 2560, bufB = buf * 2112;
#pragma unroll
        for (int i = 0; i < 2; i++) {
            int idx = i * 256 + tid;
            int r = idx >> 2, cq = idx & 3;            // A: 128 rows x 4 quads
            const float* srcH = Ah + (size_t)(bm + r) * lda + k0 + cq * 4;
            const float* srcL = Al + (size_t)(bm + r) * lda + k0 + cq * 4;
            uint32_t d = (uint32_t)(r * 20 + cq * 4) * 4;
            cpa16(sbase + (OFF_AH + bufA) * 4 + d, srcH);
            cpa16(sbase + (OFF_AL + bufA) * 4 + d, srcL);
        }
#pragma unroll
        for (int i = 0; i < 8; i++) {
            int idx = i * 256 + tid;
            int kr = idx >> 7, nc = idx & 127;         // B: 16 k x 128 n
            int c = bn + nc;
            uint32_t d = (uint32_t)(kr * 132 + nc) * 4;
            if (c < N) {
                cpa4(sbase + (OFF_BH + bufB) * 4 + d, Bh + (size_t)(k0 + kr) * ldb + c);
                cpa4(sbase + (OFF_BL + bufB) * 4 + d, Bl + (size_t)(k0 + kr) * ldb + c);
            } else {
                sm[OFF_BH + bufB + kr * 132 + nc] = 0.f;
                sm[OFF_BL + bufB + kr * 132 + nc] = 0.f;
            }
        }
    };

    load_tiles(0, 0);
    asm volatile("cp.async.commit_group;" ::: "memory");

    float4 acc[4][4];
#pragma unroll
    for (int mt = 0; mt < 4; mt++)
#pragma unroll
        for (int nt = 0; nt < 4; nt++) acc[mt][nt] = make_float4(0.f, 0.f, 0.f, 0.f);

    const uint32_t* smu = (const uint32_t*)sm;
    int T = K >> 4;
    int buf = 0;
    for (int t = 0; t < T; t++) {
        asm volatile("cp.async.wait_group 0;" ::: "memory");
        __syncthreads();
        if (t + 1 < T) {
            load_tiles((t + 1) << 4, buf ^ 1);
            asm volatile("cp.async.commit_group;" ::: "memory");
        }
        int bufA = buf * 2560, bufB = buf * 2112;
#pragma unroll
        for (int ks = 0; ks < 2; ks++) {
            int kb = ks * 8;
            uint32_t Af[4][4], Bf[4][2], Bf2[4][2];
            // hi*hi
#pragma unroll
            for (int mt = 0; mt < 4; mt++)
#pragma unroll
                for (int r = 0; r < 4; r++) {
                    int row = wm * 64 + mt * 16 + g + (r & 1) * 8;
                    int col = kb + tig + (r >> 1) * 4;
                    Af[mt][r] = smu[OFF_AH + bufA + row * 20 + col];
                }
#pragma unroll
            for (int nt = 0; nt < 4; nt++)
#pragma unroll
                for (int r = 0; r < 2; r++) {
                    int kr = kb + tig + r * 4;
                    int col = wn * 32 + nt * 8 + g;
                    Bf[nt][r]  = smu[OFF_BH + bufB + kr * 132 + col];
                    Bf2[nt][r] = smu[OFF_BL + bufB + kr * 132 + col];
                }
#pragma unroll
            for (int mt = 0; mt < 4; mt++)
#pragma unroll
                for (int nt = 0; nt < 4; nt++) mma_tf32(acc[mt][nt], Af[mt], Bf[nt]);
            // hi*lo
#pragma unroll
            for (int mt = 0; mt < 4; mt++)
#pragma unroll
                for (int nt = 0; nt < 4; nt++) mma_tf32(acc[mt][nt], Af[mt], Bf2[nt]);
            // lo*hi (reload A as lo; Bh still in Bf)
#pragma unroll
            for (int mt = 0; mt < 4; mt++)
#pragma unroll
                for (int r = 0; r < 4; r++) {
                    int row = wm * 64 + mt * 16 + g + (r & 1) * 8;
                    int col = kb + tig + (r >> 1) * 4;
                    Af[mt][r] = smu[OFF_AL + bufA + row * 20 + col];
                }
#pragma unroll
            for (int mt = 0; mt < 4; mt++)
#pragma unroll
                for (int nt = 0; nt < 4; nt++) mma_tf32(acc[mt][nt], Af[mt], Bf[nt]);
        }
        buf ^= 1;
    }

    // ---- epilogue (same fragment map as the passing R7 kernel)
#pragma unroll
    for (int mt = 0; mt < 4; mt++) {
        int row0 = bm + wm * 64 + mt * 16 + g;
#pragma unroll
        for (int nt = 0; nt < 4; nt++) {
            int col0 = bn + wn * 32 + nt * 8 + tig * 2;
            float vals[4] = {acc[mt][nt].x, acc[mt][nt].y, acc[mt][nt].z, acc[mt][nt].w};
#pragma unroll
            for (int half = 0; half < 2; half++) {
                int r = row0 + half * 8;
#pragma unroll
                for (int jj = 0; jj < 2; jj++) {
                    int c = col0 + jj;
                    if (c < N) {
                        float v = vals[half * 2 + jj];
                        if (bias) v += bias[c];
                        if (addv) v += addv[(size_t)r * ldc + c];
                        C[(size_t)r * ldc + c] = v;
                    }
                }
            }
        }
    }
}

// ---------------- attention scores: S[h,q,k] = Q·K / 8 (skip masked blocks)-
__global__ void attn_scores(const float* __restrict__ Q, const float* __restrict__ Kmat,
                            float* __restrict__ Sc) {
    int h = blockIdx.z;
    int bm = blockIdx.y * 64, bn = blockIdx.x * 64;
    if (bn > bm + 63) return;
    __shared__ float Qs[64][68];
    __shared__ float Ks[64][68];
    int tx = threadIdx.x, ty = threadIdx.y;
    int tid = ty * 16 + tx;
#pragma unroll
    for (int i = 0; i < 16; i++) {
        int e = tid + i * 256;
        int r = e >> 6, c = e & 63;
        Qs[r][c] = Q[(size_t)(bm + r) * DM_ + h * DH_ + c];
        Ks[r][c] = Kmat[(size_t)(bn + r) * DM_ + h * DH_ + c];
    }
    __syncthreads();
    float acc[4][4] = {};
#pragma unroll 8
    for (int kk = 0; kk < 64; kk++) {
        float a[4], b[4];
#pragma unroll
        for (int i = 0; i < 4; i++) a[i] = Qs[ty * 4 + i][kk];
#pragma unroll
        for (int j = 0; j < 4; j++) b[j] = Ks[tx * 4 + j][kk];
#pragma unroll
        for (int i = 0; i < 4; i++)
#pragma unroll
            for (int j = 0; j < 4; j++) acc[i][j] += a[i] * b[j];
    }
    float* Sh = Sc + (size_t)h * S_ * S_;
#pragma unroll
    for (int i = 0; i < 4; i++)
#pragma unroll
        for (int j = 0; j < 4; j++)
            Sh[(size_t)(bm + ty * 4 + i) * S_ + bn + tx * 4 + j] = acc[i][j] * 0.125f;
}

// ---------------- causal softmax over each (h,q) row ------------------------
__global__ void softmax_causal(float* __restrict__ Sc) {
    int q = blockIdx.x, h = blockIdx.y;
    float* row = Sc + ((size_t)h * S_ + q) * S_;
    int vlen = q + 1;
    int t = threadIdx.x;
    __shared__ float red[8];
    float m = -3.4e38f;
    for (int k = t; k < vlen; k += 256) m = fmaxf(m, row[k]);
#pragma unroll
    for (int o = 16; o; o >>= 1) m = fmaxf(m, __shfl_xor_sync(0xffffffffu, m, o));
    if ((t & 31) == 0) red[t >> 5] = m;
    __syncthreads();
    m = red[0];
#pragma unroll
    for (int j = 1; j < 8; j++) m = fmaxf(m, red[j]);
    __syncthreads();
    float s = 0.f;
    for (int k = t; k < vlen; k += 256) {
        float e = expf(row[k] - m);
        row[k] = e;
        s += e;
    }
#pragma unroll
    for (int o = 16; o; o >>= 1) s += __shfl_xor_sync(0xffffffffu, s, o);
    if ((t & 31) == 0) red[t >> 5] = s;
    __syncthreads();
    float tot = 0.f;
#pragma unroll
    for (int j = 0; j < 8; j++) tot += red[j];
    float inv = 1.f / tot;
    for (int k = t; k < vlen; k += 256) row[k] *= inv;
    int blkend = ((q >> 6) + 1) << 6;
    for (int k = vlen + t; k < blkend; k += 256) row[k] = 0.f;
}

// ---------------- Z[q, h*64+e] = sum_k P[h,q,k] * V[k, h*64+e] -------------
__global__ void attn_z(const float* __restrict__ P, const float* __restrict__ Vm,
                       float* __restrict__ Z) {
    int h = blockIdx.z;
    int bm = blockIdx.y * 64;
    const float* Ph = P + (size_t)h * S_ * S_;
    __shared__ float Ps[64][17];
    __shared__ float Vs[16][68];
    int tx = threadIdx.x, ty = threadIdx.y;
    int tid = ty * 16 + tx;
    float acc[4][4] = {};
    int kmax = bm + 64;
    for (int k0 = 0; k0 < kmax; k0 += 16) {
#pragma unroll
        for (int i = 0; i < 4; i++) {
            int e = tid + i * 256;
            int r = e >> 4, c = e & 15;
            Ps[r][c] = Ph[(size_t)(bm + r) * S_ + k0 + c];
        }
#pragma unroll
        for (int i = 0; i < 4; i++) {
            int e = tid + i * 256;
            int r = e >> 6, c = e & 63;
            Vs[r][c] = Vm[(size_t)(k0 + r) * DM_ + h * DH_ + c];
        }
        __syncthreads();
#pragma unroll
        for (int kk = 0; kk < 16; kk++) {
            float a[4], b[4];
#pragma unroll
            for (int i = 0; i < 4; i++) a[i] = Ps[ty * 4 + i][kk];
#pragma unroll
            for (int j = 0; j < 4; j++) b[j] = Vs[kk][tx * 4 + j];
#pragma unroll
            for (int i = 0; i < 4; i++)
#pragma unroll
                for (int j = 0; j < 4; j++) acc[i][j] += a[i] * b[j];
        }
        __syncthreads();
    }
#pragma unroll
    for (int i = 0; i < 4; i++)
#pragma unroll
        for (int j = 0; j < 4; j++)
            Z[(size_t)(bm + ty * 4 + i) * DM_ + h * DH_ + tx * 4 + j] = acc[i][j];
}

// ---------------- exact GELU ------------------------------------------------
__global__ void gelu_kernel(const float* __restrict__ X, float* __restrict__ Y, int n) {
    int i = blockIdx.x * 256 + threadIdx.x;
    if (i < n) {
        float x = X[i];
        Y[i] = 0.5f * x * (1.f + erff(x * 0.70710678118654752f));
    }
}

// ---------------- copy ------------------------------------------------------
__global__ void copy_kernel(const float* __restrict__ a, float* __restrict__ b, int n) {
    int i = blockIdx.x * 256 + threadIdx.x;
    if (i < n) b[i] = a[i];
}

// ---------------- host driver ----------------------------------------------
extern "C" void kernel_launch(void* const* d_in, const int* in_sizes, int n_in,
                              void* d_out, int out_size) {
    const int*   tokens = (const int*)  d_in[0];
    const float* W_E    = (const float*)d_in[1];
    const float* W_pos  = (const float*)d_in[2];
    const float* ln1_w  = (const float*)d_in[3];
    const float* ln1_b  = (const float*)d_in[4];
    const float* W_Q    = (const float*)d_in[5];
    const float* b_Q    = (const float*)d_in[6];
    const float* W_K    = (const float*)d_in[7];
    const float* b_K    = (const float*)d_in[8];
    const float* W_V    = (const float*)d_in[9];
    const float* b_V    = (const float*)d_in[10];
    const float* W_O    = (const float*)d_in[11];
    const float* b_O    = (const float*)d_in[12];
    const float* ln2_w  = (const float*)d_in[13];
    const float* ln2_b  = (const float*)d_in[14];
    const float* W_in   = (const float*)d_in[15];
    const float* b_in   = (const float*)d_in[16];
    const float* W_out  = (const float*)d_in[17];
    const float* b_out  = (const float*)d_in[18];
    const float* lnf_w  = (const float*)d_in[19];
    const float* lnf_b  = (const float*)d_in[20];
    const float* W_U    = (const float*)d_in[21];
    const float* b_U    = (const float*)d_in[22];
    float* out = (float*)d_out;

    float *resid, *x, *q, *k, *v, *z, *sc, *pre, *post, *Ah, *Al, *Bh, *Bl;
    cudaGetSymbolAddress((void**)&resid, g_resid);
    cudaGetSymbolAddress((void**)&x,     g_x);
    cudaGetSymbolAddress((void**)&q,     g_q);
    cudaGetSymbolAddress((void**)&k,     g_k);
    cudaGetSymbolAddress((void**)&v,     g_v);
    cudaGetSymbolAddress((void**)&z,     g_z);
    cudaGetSymbolAddress((void**)&sc,    g_scores);
    cudaGetSymbolAddress((void**)&pre,   g_pre);
    cudaGetSymbolAddress((void**)&post,  g_post);
    cudaGetSymbolAddress((void**)&Ah,    g_Ah);
    cudaGetSymbolAddress((void**)&Al,    g_Al);
    cudaGetSymbolAddress((void**)&Bh,    g_Bh);
    cudaGetSymbolAddress((void**)&Bl,    g_Bl);

    cudaFuncSetAttribute(t32gemm, cudaFuncAttributeMaxDynamicSharedMemorySize, SMEM_TG);

    dim3 t2(16, 16);
    dim3 g_dm(S_ / 128, DM_ / 128);               // x = M blocks, y = N blocks

    const int nXDM  = S_ * DM_ / 4;               // float4 counts
    const int nWDM  = DM_ * DM_ / 4;
    const int nWMLP = DM_ * DMLP_ / 4;
    const int nPOST = S_ * DMLP_ / 4;
    const int nWU   = DM_ * V_ / 4;

    embed_kernel<<<S_ * DM_ / 256, 256>>>(tokens, W_E, W_pos, resid);

    for (int l = 0; l < L_; l++) {
        layernorm1024<<<S_, 256>>>(resid, ln1_w + l * DM_, ln1_b + l * DM_, x);
        split_kernel<<<(nXDM + 255) / 256, 256>>>(x, Ah, Al, nXDM);

        repack_split_qkv<<<DM_ * DM_ / 256, 256>>>(W_Q, Bh, Bl, l);
        t32gemm<<<g_dm, 256, SMEM_TG>>>(Ah, Al, Bh, Bl, b_Q + l * DM_, nullptr, q,
                                        S_, DM_, DM_, DM_, DM_, DM_);
        repack_split_qkv<<<DM_ * DM_ / 256, 256>>>(W_K, Bh, Bl, l);
        t32gemm<<<g_dm, 256, SMEM_TG>>>(Ah, Al, Bh, Bl, b_K + l * DM_, nullptr, k,
                                        S_, DM_, DM_, DM_, DM_, DM_);
        repack_split_qkv<<<DM_ * DM_ / 256, 256>>>(W_V, Bh, Bl, l);
        t32gemm<<<g_dm, 256, SMEM_TG>>>(Ah, Al, Bh, Bl, b_V + l * DM_, nullptr, v,
                                        S_, DM_, DM_, DM_, DM_, DM_);

        attn_scores<<<dim3(S_ / 64, S_ / 64, H_), t2>>>(q, k, sc);
        softmax_causal<<<dim3(S_, H_), 256>>>(sc);
        attn_z<<<dim3(1, S_ / 64, H_), t2>>>(sc, v, z);

        split_kernel<<<(nXDM + 255) / 256, 256>>>(z, Ah, Al, nXDM);
        split_kernel<<<(nWDM + 255) / 256, 256>>>(W_O + (size_t)l * DM_ * DM_, Bh, Bl, nWDM);
        t32gemm<<<g_dm, 256, SMEM_TG>>>(Ah, Al, Bh, Bl, b_O + l * DM_, resid, resid,
                                        S_, DM_, DM_, DM_, DM_, DM_);

        layernorm1024<<<S_, 256>>>(resid, ln2_w + l * DM_, ln2_b + l * DM_, x);
        split_kernel<<<(nXDM + 255) / 256, 256>>>(x, Ah, Al, nXDM);
        split_kernel<<<(nWMLP + 255) / 256, 256>>>(W_in + (size_t)l * DM_ * DMLP_, Bh, Bl, nWMLP);
        t32gemm<<<dim3(S_ / 128, DMLP_ / 128), 256, SMEM_TG>>>(
            Ah, Al, Bh, Bl, b_in + l * DMLP_, nullptr, pre, S_, DMLP_, DM_, DM_, DMLP_, DMLP_);

        gelu_kernel<<<S_ * DMLP_ / 256, 256>>>(pre, post, S_ * DMLP_);
        split_kernel<<<(nPOST + 255) / 256, 256>>>(post, Ah, Al, nPOST);
        split_kernel<<<(nWMLP + 255) / 256, 256>>>(W_out + (size_t)l * DMLP_ * DM_, Bh, Bl, nWMLP);
        t32gemm<<<g_dm, 256, SMEM_TG>>>(Ah, Al, Bh, Bl, b_out + l * DM_, resid, resid,
                                        S_, DM_, DMLP_, DMLP_, DM_, DM_);
    }

    layernorm1024<<<S_, 256>>>(resid, lnf_w, lnf_b, x);
    split_kernel<<<(nXDM + 255) / 256, 256>>>(x, Ah, Al, nXDM);
    split_kernel<<<(nWU + 255) / 256, 256>>>(W_U, Bh, Bl, nWU);
    t32gemm<<<dim3(S_ / 128, (V_ + 127) / 128), 256, SMEM_TG>>>(
        Ah, Al, Bh, Bl, b_U, nullptr, out, S_, V_, DM_, DM_, V_, V_);

    copy_kernel<<<S_ * DM_ / 256, 256>>>(resid, out + (size_t)S_ * V_, S_ * DM_);
    copy_kernel<<<S_ * DMLP_ / 256, 256>>>(post, out + (size_t)S_ * V_ + S_ * DM_, S_ * DMLP_);
}

// round 15
// speedup vs baseline: 1.6395x; 1.2515x over previous
#include <cuda_runtime.h>
#include <cuda_bf16.h>
#include <math.h>
#include <stdint.h>

#define S_    2048
#define DM_   1024
#define DMLP_ 4096
#define V_    50257
#define H_    16
#define DH_   64
#define L_    2

// ---------------- scratch (static device memory; no allocs allowed) --------
__device__ float g_resid[S_ * DM_];
__device__ float g_x[S_ * DM_];
__device__ float g_q[S_ * DM_];
__device__ float g_k[S_ * DM_];
__device__ float g_v[S_ * DM_];
__device__ float g_z[S_ * DM_];
__device__ float g_scores[(size_t)H_ * S_ * S_];   // 268 MB
__device__ float g_pre[S_ * DMLP_];
__device__ float g_post[S_ * DMLP_];
// tf32-split staging (hi/lo hold tf32-valued fp32)
__device__ float g_Ah[S_ * DMLP_];                 // max A = post (2048x4096)
__device__ float g_Al[S_ * DMLP_];
__device__ float g_Bh[DM_ * V_];                   // max B = W_U (1024x50257)
__device__ float g_Bl[DM_ * V_];
// dedicated QKV weight buffers (lets repacks batch ahead of GEMMs)
__device__ float g_Bqh[DM_ * DM_], g_Bql[DM_ * DM_];
__device__ float g_Bkh[DM_ * DM_], g_Bkl[DM_ * DM_];
__device__ float g_Bvh[DM_ * DM_], g_Bvl[DM_ * DM_];

// ---------------- tf32 helpers ----------------------------------------------
__device__ __forceinline__ uint32_t f2tf32(float x) {
    uint32_t r;
    asm("cvt.rna.tf32.f32 %0, %1;" : "=r"(r) : "f"(x));
    return r;
}
__device__ __forceinline__ void split2(float x, float& h, float& l) {
    h = __uint_as_float(f2tf32(x));
    l = __uint_as_float(f2tf32(x - h));
}

// ---------------- embed ----------------------------------------------------
__global__ void embed_kernel(const int* __restrict__ tok,
                             const float* __restrict__ WE,
                             const float* __restrict__ Wpos,
                             float* __restrict__ out) {
    int idx = blockIdx.x * 256 + threadIdx.x;
    int s = idx >> 10;
    int d = idx & 1023;
    out[idx] = WE[(size_t)tok[s] * DM_ + d] + Wpos[idx];
}

// ---------------- elementwise tf32 split (float4), n % 4 == 0 ---------------
__global__ void split_kernel(const float* __restrict__ X,
                             float* __restrict__ hi, float* __restrict__ lo, int n4) {
    int i = blockIdx.x * 256 + threadIdx.x;
    if (i < n4) {
        float4 x = ((const float4*)X)[i];
        float4 h, l;
        split2(x.x, h.x, l.x);
        split2(x.y, h.y, l.y);
        split2(x.z, h.z, l.z);
        split2(x.w, h.w, l.w);
        ((float4*)hi)[i] = h;
        ((float4*)lo)[i] = l;
    }
}

// ------- repack W_{Q,K,V}[l] (H,DM,DH) -> [DM,H*DH] fused with tf32 split ---
__global__ void repack_split_qkv(const float* __restrict__ W,
                                 float* __restrict__ hi, float* __restrict__ lo, int l) {
    int idx = blockIdx.x * 256 + threadIdx.x;     // DM_*DM_
    int d = idx >> 10;
    int n = idx & 1023;
    int h = n >> 6;
    int e = n & 63;
    float x = W[(size_t)(((l * H_ + h) * DM_) + d) * DH_ + e];
    float xh, xl;
    split2(x, xh, xl);
    hi[idx] = xh;
    lo[idx] = xl;
}

// ---------------- layernorm over 1024 cols, one block per row --------------
__global__ void layernorm1024(const float* __restrict__ X,
                              const float* __restrict__ w,
                              const float* __restrict__ b,
                              float* __restrict__ Y) {
    int row = blockIdx.x;
    const float* x = X + (size_t)row * DM_;
    int t = threadIdx.x;
    __shared__ float red[8];
    float v[4];
#pragma unroll
    for (int i = 0; i < 4; i++) v[i] = x[t + i * 256];
    float s = v[0] + v[1] + v[2] + v[3];
#pragma unroll
    for (int o = 16; o; o >>= 1) s += __shfl_xor_sync(0xffffffffu, s, o);
    if ((t & 31) == 0) red[t >> 5] = s;
    __syncthreads();
    float mean = 0.f;
#pragma unroll
    for (int j = 0; j < 8; j++) mean += red[j];
    mean *= (1.f / DM_);
    __syncthreads();
    float sq = 0.f;
#pragma unroll
    for (int i = 0; i < 4; i++) { float d = v[i] - mean; sq += d * d; }
#pragma unroll
    for (int o = 16; o; o >>= 1) sq += __shfl_xor_sync(0xffffffffu, sq, o);
    if ((t & 31) == 0) red[t >> 5] = sq;
    __syncthreads();
    float var = 0.f;
#pragma unroll
    for (int j = 0; j < 8; j++) var += red[j];
    var *= (1.f / DM_);
    float inv = rsqrtf(var + 1e-5f);
    float* y = Y + (size_t)row * DM_;
#pragma unroll
    for (int i = 0; i < 4; i++) {
        int c = t + i * 256;
        y[c] = (v[i] - mean) * inv * w[c] + b[c];
    }
}

// ---------------- mma + cp.async helpers ------------------------------------
__device__ __forceinline__ void mma_tf32(float4& d, const uint32_t a[4], const uint32_t b[2]) {
    asm volatile(
        "mma.sync.aligned.m16n8k8.row.col.f32.tf32.tf32.f32 "
        "{%0,%1,%2,%3}, {%4,%5,%6,%7}, {%8,%9}, {%0,%1,%2,%3};"
        : "+f"(d.x), "+f"(d.y), "+f"(d.z), "+f"(d.w)
        : "r"(a[0]), "r"(a[1]), "r"(a[2]), "r"(a[3]), "r"(b[0]), "r"(b[1]));
}
__device__ __forceinline__ void cpa16(uint32_t dst, const void* src) {
    asm volatile("cp.async.ca.shared.global [%0], [%1], 16;" :: "r"(dst), "l"(src));
}
__device__ __forceinline__ void cpa4(uint32_t dst, const void* src) {
    asm volatile("cp.async.ca.shared.global [%0], [%1], 4;" :: "r"(dst), "l"(src));
}
__device__ __forceinline__ uint32_t smem_u32(const void* p) {
    uint32_t a;
    asm("{ .reg .u64 t; cvta.to.shared.u64 t, %1; cvt.u32.u64 %0, t; }" : "=r"(a) : "l"(p));
    return a;
}

// -------- tensor-core GEMM, presplit TF32, cp.async double-buffered ---------
// C = A @ B (+bias +addv). Operands given as tf32 hi/lo fp32 arrays.
// nterms: 3 = full 3xTF32 (fp32-class accuracy); 1 = hi*hi only (~5e-4).
// M%128==0, K%16==0, lda%4==0. N ragged OK.
#define OFF_AH 0
#define OFF_AL 5120
#define OFF_BH 10240
#define OFF_BL 14464
#define SM_FLOATS 18688
#define SMEM_TG (SM_FLOATS * 4)

__global__ __launch_bounds__(256, 2)
void t32gemm(const float* __restrict__ Ah, const float* __restrict__ Al,
             const float* __restrict__ Bh, const float* __restrict__ Bl,
             const float* __restrict__ bias, const float* __restrict__ addv,
             float* __restrict__ C, int M, int N, int K, int lda, int ldb, int ldc,
             int nterms) {
    extern __shared__ float sm[];
    uint32_t sbase = smem_u32(sm);

    int tid  = threadIdx.x;
    int lane = tid & 31;
    int warp = tid >> 5;
    int g    = lane >> 2;
    int tig  = lane & 3;
    int wm   = warp >> 2;
    int wn   = warp & 3;
    int bm = blockIdx.x * 128, bn = blockIdx.y * 128;

    // ---- async tile load: A (16B) + B (4B, guarded)
    auto load_tiles = [&](int k0, int buf) {
        int bufA = buf * 2560, bufB = buf * 2112;
#pragma unroll
        for (int i = 0; i < 2; i++) {
            int idx = i * 256 + tid;
            int r = idx >> 2, cq = idx & 3;            // A: 128 rows x 4 quads
            uint32_t d = (uint32_t)(r * 20 + cq * 4) * 4;
            cpa16(sbase + (OFF_AH + bufA) * 4 + d, Ah + (size_t)(bm + r) * lda + k0 + cq * 4);
            if (nterms == 3)
                cpa16(sbase + (OFF_AL + bufA) * 4 + d, Al + (size_t)(bm + r) * lda + k0 + cq * 4);
        }
#pragma unroll
        for (int i = 0; i < 8; i++) {
            int idx = i * 256 + tid;
            int kr = idx >> 7, nc = idx & 127;         // B: 16 k x 128 n
            int c = bn + nc;
            uint32_t d = (uint32_t)(kr * 132 + nc) * 4;
            if (c < N) {
                cpa4(sbase + (OFF_BH + bufB) * 4 + d, Bh + (size_t)(k0 + kr) * ldb + c);
                if (nterms == 3)
                    cpa4(sbase + (OFF_BL + bufB) * 4 + d, Bl + (size_t)(k0 + kr) * ldb + c);
            } else {
                sm[OFF_BH + bufB + kr * 132 + nc] = 0.f;
                sm[OFF_BL + bufB + kr * 132 + nc] = 0.f;
            }
        }
    };

    load_tiles(0, 0);
    asm volatile("cp.async.commit_group;" ::: "memory");

    float4 acc[4][4];
#pragma unroll
    for (int mt = 0; mt < 4; mt++)
#pragma unroll
        for (int nt = 0; nt < 4; nt++) acc[mt][nt] = make_float4(0.f, 0.f, 0.f, 0.f);

    const uint32_t* smu = (const uint32_t*)sm;
    int T = K >> 4;
    int buf = 0;
    for (int t = 0; t < T; t++) {
        asm volatile("cp.async.wait_group 0;" ::: "memory");
        __syncthreads();
        if (t + 1 < T) {
            load_tiles((t + 1) << 4, buf ^ 1);
            asm volatile("cp.async.commit_group;" ::: "memory");
        }
        int bufA = buf * 2560, bufB = buf * 2112;
#pragma unroll
        for (int ks = 0; ks < 2; ks++) {
            int kb = ks * 8;
            uint32_t Af[4][4], Bf[4][2];
            // hi*hi
#pragma unroll
            for (int mt = 0; mt < 4; mt++)
#pragma unroll
                for (int r = 0; r < 4; r++) {
                    int row = wm * 64 + mt * 16 + g + (r & 1) * 8;
                    int col = kb + tig + (r >> 1) * 4;
                    Af[mt][r] = smu[OFF_AH + bufA + row * 20 + col];
                }
#pragma unroll
            for (int nt = 0; nt < 4; nt++)
#pragma unroll
                for (int r = 0; r < 2; r++) {
                    int kr = kb + tig + r * 4;
                    int col = wn * 32 + nt * 8 + g;
                    Bf[nt][r] = smu[OFF_BH + bufB + kr * 132 + col];
                }
#pragma unroll
            for (int mt = 0; mt < 4; mt++)
#pragma unroll
                for (int nt = 0; nt < 4; nt++) mma_tf32(acc[mt][nt], Af[mt], Bf[nt]);
            if (nterms == 3) {
                // hi*lo
                uint32_t Bf2[4][2];
#pragma unroll
                for (int nt = 0; nt < 4; nt++)
#pragma unroll
                    for (int r = 0; r < 2; r++) {
                        int kr = kb + tig + r * 4;
                        int col = wn * 32 + nt * 8 + g;
                        Bf2[nt][r] = smu[OFF_BL + bufB + kr * 132 + col];
                    }
#pragma unroll
                for (int mt = 0; mt < 4; mt++)
#pragma unroll
                    for (int nt = 0; nt < 4; nt++) mma_tf32(acc[mt][nt], Af[mt], Bf2[nt]);
                // lo*hi
#pragma unroll
                for (int mt = 0; mt < 4; mt++)
#pragma unroll
                    for (int r = 0; r < 4; r++) {
                        int row = wm * 64 + mt * 16 + g + (r & 1) * 8;
                        int col = kb + tig + (r >> 1) * 4;
                        Af[mt][r] = smu[OFF_AL + bufA + row * 20 + col];
                    }
#pragma unroll
                for (int mt = 0; mt < 4; mt++)
#pragma unroll
                    for (int nt = 0; nt < 4; nt++) mma_tf32(acc[mt][nt], Af[mt], Bf[nt]);
            }
        }
        buf ^= 1;
    }

    // ---- epilogue (same fragment map as the passing R7/R14 kernels)
#pragma unroll
    for (int mt = 0; mt < 4; mt++) {
        int row0 = bm + wm * 64 + mt * 16 + g;
#pragma unroll
        for (int nt = 0; nt < 4; nt++) {
            int col0 = bn + wn * 32 + nt * 8 + tig * 2;
            float vals[4] = {acc[mt][nt].x, acc[mt][nt].y, acc[mt][nt].z, acc[mt][nt].w};
#pragma unroll
            for (int half = 0; half < 2; half++) {
                int r = row0 + half * 8;
#pragma unroll
                for (int jj = 0; jj < 2; jj++) {
                    int c = col0 + jj;
                    if (c < N) {
                        float v = vals[half * 2 + jj];
                        if (bias) v += bias[c];
                        if (addv) v += addv[(size_t)r * ldc + c];
                        C[(size_t)r * ldc + c] = v;
                    }
                }
            }
        }
    }
}

// ---------------- attention scores: S[h,q,k] = Q·K / 8 (skip masked blocks)-
__global__ void attn_scores(const float* __restrict__ Q, const float* __restrict__ Kmat,
                            float* __restrict__ Sc) {
    int h = blockIdx.z;
    int bm = blockIdx.y * 64, bn = blockIdx.x * 64;
    if (bn > bm + 63) return;
    __shared__ float Qs[64][68];
    __shared__ float Ks[64][68];
    int tx = threadIdx.x, ty = threadIdx.y;
    int tid = ty * 16 + tx;
#pragma unroll
    for (int i = 0; i < 16; i++) {
        int e = tid + i * 256;
        int r = e >> 6, c = e & 63;
        Qs[r][c] = Q[(size_t)(bm + r) * DM_ + h * DH_ + c];
        Ks[r][c] = Kmat[(size_t)(bn + r) * DM_ + h * DH_ + c];
    }
    __syncthreads();
    float acc[4][4] = {};
#pragma unroll 8
    for (int kk = 0; kk < 64; kk++) {
        float a[4], b[4];
#pragma unroll
        for (int i = 0; i < 4; i++) a[i] = Qs[ty * 4 + i][kk];
#pragma unroll
        for (int j = 0; j < 4; j++) b[j] = Ks[tx * 4 + j][kk];
#pragma unroll
        for (int i = 0; i < 4; i++)
#pragma unroll
            for (int j = 0; j < 4; j++) acc[i][j] += a[i] * b[j];
    }
    float* Sh = Sc + (size_t)h * S_ * S_;
#pragma unroll
    for (int i = 0; i < 4; i++)
#pragma unroll
        for (int j = 0; j < 4; j++)
            Sh[(size_t)(bm + ty * 4 + i) * S_ + bn + tx * 4 + j] = acc[i][j] * 0.125f;
}

// ---------------- causal softmax over each (h,q) row ------------------------
__global__ void softmax_causal(float* __restrict__ Sc) {
    int q = blockIdx.x, h = blockIdx.y;
    float* row = Sc + ((size_t)h * S_ + q) * S_;
    int vlen = q + 1;
    int t = threadIdx.x;
    __shared__ float red[8];
    float m = -3.4e38f;
    for (int k = t; k < vlen; k += 256) m = fmaxf(m, row[k]);
#pragma unroll
    for (int o = 16; o; o >>= 1) m = fmaxf(m, __shfl_xor_sync(0xffffffffu, m, o));
    if ((t & 31) == 0) red[t >> 5] = m;
    __syncthreads();
    m = red[0];
#pragma unroll
    for (int j = 1; j < 8; j++) m = fmaxf(m, red[j]);
    __syncthreads();
    float s = 0.f;
    for (int k = t; k < vlen; k += 256) {
        float e = expf(row[k] - m);
        row[k] = e;
        s += e;
    }
#pragma unroll
    for (int o = 16; o; o >>= 1) s += __shfl_xor_sync(0xffffffffu, s, o);
    if ((t & 31) == 0) red[t >> 5] = s;
    __syncthreads();
    float tot = 0.f;
#pragma unroll
    for (int j = 0; j < 8; j++) tot += red[j];
    float inv = 1.f / tot;
    for (int k = t; k < vlen; k += 256) row[k] *= inv;
    int blkend = ((q >> 6) + 1) << 6;
    for (int k = vlen + t; k < blkend; k += 256) row[k] = 0.f;
}

// ---------------- Z[q, h*64+e] = sum_k P[h,q,k] * V[k, h*64+e] -------------
__global__ void attn_z(const float* __restrict__ P, const float* __restrict__ Vm,
                       float* __restrict__ Z) {
    int h = blockIdx.z;
    int bm = blockIdx.y * 64;
    const float* Ph = P + (size_t)h * S_ * S_;
    __shared__ float Ps[64][17];
    __shared__ float Vs[16][68];
    int tx = threadIdx.x, ty = threadIdx.y;
    int tid = ty * 16 + tx;
    float acc[4][4] = {};
    int kmax = bm + 64;
    for (int k0 = 0; k0 < kmax; k0 += 16) {
#pragma unroll
        for (int i = 0; i < 4; i++) {
            int e = tid + i * 256;
            int r = e >> 4, c = e & 15;
            Ps[r][c] = Ph[(size_t)(bm + r) * S_ + k0 + c];
        }
#pragma unroll
        for (int i = 0; i < 4; i++) {
            int e = tid + i * 256;
            int r = e >> 6, c = e & 63;
            Vs[r][c] = Vm[(size_t)(k0 + r) * DM_ + h * DH_ + c];
        }
        __syncthreads();
#pragma unroll
        for (int kk = 0; kk < 16; kk++) {
            float a[4], b[4];
#pragma unroll
            for (int i = 0; i < 4; i++) a[i] = Ps[ty * 4 + i][kk];
#pragma unroll
            for (int j = 0; j < 4; j++) b[j] = Vs[kk][tx * 4 + j];
#pragma unroll
            for (int i = 0; i < 4; i++)
#pragma unroll
                for (int j = 0; j < 4; j++) acc[i][j] += a[i] * b[j];
        }
        __syncthreads();
    }
#pragma unroll
    for (int i = 0; i < 4; i++)
#pragma unroll
        for (int j = 0; j < 4; j++)
            Z[(size_t)(bm + ty * 4 + i) * DM_ + h * DH_ + tx * 4 + j] = acc[i][j];
}

// ---------------- exact GELU ------------------------------------------------
__global__ void gelu_kernel(const float* __restrict__ X, float* __restrict__ Y, int n) {
    int i = blockIdx.x * 256 + threadIdx.x;
    if (i < n) {
        float x = X[i];
        Y[i] = 0.5f * x * (1.f + erff(x * 0.70710678118654752f));
    }
}

// ---------------- copy ------------------------------------------------------
__global__ void copy_kernel(const float* __restrict__ a, float* __restrict__ b, int n) {
    int i = blockIdx.x * 256 + threadIdx.x;
    if (i < n) b[i] = a[i];
}

// ---------------- host driver ----------------------------------------------
extern "C" void kernel_launch(void* const* d_in, const int* in_sizes, int n_in,
                              void* d_out, int out_size) {
    const int*   tokens = (const int*)  d_in[0];
    const float* W_E    = (const float*)d_in[1];
    const float* W_pos  = (const float*)d_in[2];
    const float* ln1_w  = (const float*)d_in[3];
    const float* ln1_b  = (const float*)d_in[4];
    const float* W_Q    = (const float*)d_in[5];
    const float* b_Q    = (const float*)d_in[6];
    const float* W_K    = (const float*)d_in[7];
    const float* b_K    = (const float*)d_in[8];
    const float* W_V    = (const float*)d_in[9];
    const float* b_V    = (const float*)d_in[10];
    const float* W_O    = (const float*)d_in[11];
    const float* b_O    = (const float*)d_in[12];
    const float* ln2_w  = (const float*)d_in[13];
    const float* ln2_b  = (const float*)d_in[14];
    const float* W_in   = (const float*)d_in[15];
    const float* b_in   = (const float*)d_in[16];
    const float* W_out  = (const float*)d_in[17];
    const float* b_out  = (const float*)d_in[18];
    const float* lnf_w  = (const float*)d_in[19];
    const float* lnf_b  = (const float*)d_in[20];
    const float* W_U    = (const float*)d_in[21];
    const float* b_U    = (const float*)d_in[22];
    float* out = (float*)d_out;

    float *resid, *x, *q, *k, *v, *z, *sc, *pre, *post, *Ah, *Al, *Bh, *Bl;
    float *Bqh, *Bql, *Bkh, *Bkl, *Bvh, *Bvl;
    cudaGetSymbolAddress((void**)&resid, g_resid);
    cudaGetSymbolAddress((void**)&x,     g_x);
    cudaGetSymbolAddress((void**)&q,     g_q);
    cudaGetSymbolAddress((void**)&k,     g_k);
    cudaGetSymbolAddress((void**)&v,     g_v);
    cudaGetSymbolAddress((void**)&z,     g_z);
    cudaGetSymbolAddress((void**)&sc,    g_scores);
    cudaGetSymbolAddress((void**)&pre,   g_pre);
    cudaGetSymbolAddress((void**)&post,  g_post);
    cudaGetSymbolAddress((void**)&Ah,    g_Ah);
    cudaGetSymbolAddress((void**)&Al,    g_Al);
    cudaGetSymbolAddress((void**)&Bh,    g_Bh);
    cudaGetSymbolAddress((void**)&Bl,    g_Bl);
    cudaGetSymbolAddress((void**)&Bqh,   g_Bqh);
    cudaGetSymbolAddress((void**)&Bql,   g_Bql);
    cudaGetSymbolAddress((void**)&Bkh,   g_Bkh);
    cudaGetSymbolAddress((void**)&Bkl,   g_Bkl);
    cudaGetSymbolAddress((void**)&Bvh,   g_Bvh);
    cudaGetSymbolAddress((void**)&Bvl,   g_Bvl);

    cudaFuncSetAttribute(t32gemm, cudaFuncAttributeMaxDynamicSharedMemorySize, SMEM_TG);

    dim3 t2(16, 16);
    dim3 g_dm(S_ / 128, DM_ / 128);               // x = M blocks, y = N blocks

    const int nXDM  = S_ * DM_ / 4;               // float4 counts
    const int nWDM  = DM_ * DM_ / 4;
    const int nWMLP = DM_ * DMLP_ / 4;
    const int nPOST = S_ * DMLP_ / 4;
    const int nWU   = DM_ * V_ / 4;

    embed_kernel<<<S_ * DM_ / 256, 256>>>(tokens, W_E, W_pos, resid);          // 0

    for (int l = 0; l < L_; l++) {
        layernorm1024<<<S_, 256>>>(resid, ln1_w + l * DM_, ln1_b + l * DM_, x); // 1
        split_kernel<<<(nXDM + 255) / 256, 256>>>(x, Ah, Al, nXDM);             // 2
        repack_split_qkv<<<DM_ * DM_ / 256, 256>>>(W_Q, Bqh, Bql, l);           // 3
        repack_split_qkv<<<DM_ * DM_ / 256, 256>>>(W_K, Bkh, Bkl, l);           // 4
        t32gemm<<<g_dm, 256, SMEM_TG>>>(Ah, Al, Bqh, Bql, b_Q + l * DM_, nullptr, q,
                                        S_, DM_, DM_, DM_, DM_, DM_, 3);        // 5 <- ncu
        repack_split_qkv<<<DM_ * DM_ / 256, 256>>>(W_V, Bvh, Bvl, l);
        t32gemm<<<g_dm, 256, SMEM_TG>>>(Ah, Al, Bkh, Bkl, b_K + l * DM_, nullptr, k,
                                        S_, DM_, DM_, DM_, DM_, DM_, 3);
        t32gemm<<<g_dm, 256, SMEM_TG>>>(Ah, Al, Bvh, Bvl, b_V + l * DM_, nullptr, v,
                                        S_, DM_, DM_, DM_, DM_, DM_, 3);

        attn_scores<<<dim3(S_ / 64, S_ / 64, H_), t2>>>(q, k, sc);
        softmax_causal<<<dim3(S_, H_), 256>>>(sc);
        attn_z<<<dim3(1, S_ / 64, H_), t2>>>(sc, v, z);

        split_kernel<<<(nXDM + 255) / 256, 256>>>(z, Ah, Al, nXDM);
        split_kernel<<<(nWDM + 255) / 256, 256>>>(W_O + (size_t)l * DM_ * DM_, Bh, Bl, nWDM);
        t32gemm<<<g_dm, 256, SMEM_TG>>>(Ah, Al, Bh, Bl, b_O + l * DM_, resid, resid,
                                        S_, DM_, DM_, DM_, DM_, DM_, 3);

        layernorm1024<<<S_, 256>>>(resid, ln2_w + l * DM_, ln2_b + l * DM_, x);
        split_kernel<<<(nXDM + 255) / 256, 256>>>(x, Ah, Al, nXDM);
        split_kernel<<<(nWMLP + 255) / 256, 256>>>(W_in + (size_t)l * DM_ * DMLP_, Bh, Bl, nWMLP);
        t32gemm<<<dim3(S_ / 128, DMLP_ / 128), 256, SMEM_TG>>>(
            Ah, Al, Bh, Bl, b_in + l * DMLP_, nullptr, pre, S_, DMLP_, DM_, DM_, DMLP_, DMLP_, 3);

        gelu_kernel<<<S_ * DMLP_ / 256, 256>>>(pre, post, S_ * DMLP_);
        split_kernel<<<(nPOST + 255) / 256, 256>>>(post, Ah, Al, nPOST);
        split_kernel<<<(nWMLP + 255) / 256, 256>>>(W_out + (size_t)l * DMLP_ * DM_, Bh, Bl, nWMLP);
        t32gemm<<<g_dm, 256, SMEM_TG>>>(Ah, Al, Bh, Bl, b_out + l * DM_, resid, resid,
                                        S_, DM_, DMLP_, DMLP_, DM_, DM_, 3);
    }

    layernorm1024<<<S_, 256>>>(resid, lnf_w, lnf_b, x);
    split_kernel<<<(nXDM + 255) / 256, 256>>>(x, Ah, Al, nXDM);
    split_kernel<<<(nWU + 255) / 256, 256>>>(W_U, Bh, Bl, nWU);
    // unembed: 1xTF32 (hi*hi only) — logits error ~3e-4, within 1e-3 budget
    t32gemm<<<dim3(S_ / 128, (V_ + 127) / 128), 256, SMEM_TG>>>(
        Ah, Al, Bh, Bl, b_U, nullptr, out, S_, V_, DM_, DM_, V_, V_, 1);

    copy_kernel<<<S_ * DM_ / 256, 256>>>(resid, out + (size_t)S_ * V_, S_ * DM_);
    copy_kernel<<<S_ * DMLP_ / 256, 256>>>(post, out + (size_t)S_ * V_ + S_ * DM_, S_ * DMLP_);
}